// round 16
// baseline (speedup 1.0000x reference)
#include <cuda_runtime.h>
#include <cuda_fp16.h>
#include <cstdint>
#include <cstddef>

// out[h,n,m] = LeakyReLU_{0.2}( sum_d z0[n,d]*z1[m,d]*W[h,d] + bias[h] )
// N=M=1024, D=256, H=128, fp32 in/out.
//
// v16 = v15 (best: deferred stores, hs=2, merged prep) + cross-h software
// pipelining: h-loop unrolled x2 so ptxas interleaves adjacent h bodies
// (acc-init / W-preload / epilogue of one h hide under the other's MMAs).
// CTA = 16n x 64m x 64h; grid = 2048; 3 CTAs/SM.

#define NT 128

__device__ uint4 g_z0f[64 * 16 * 32];      // [n16tile][ks][lane] {a0,a1,a2,a3}  512KB
__device__ uint4 g_z1f[128 * 8 * 32];      // [m8tile][kspair][lane]             512KB
__device__ uint4 g_wf[128 * 8 * 4];        // [h][ksp][c] {w01a,w89a,w01b,w89b}  64KB

static constexpr int SM_BIAS = 32768;            // after 32KB W slice
static constexpr int SMEM_BYTES = 32768 + 256;

__device__ __forceinline__ uint32_t smem_u32(const void* p) {
    uint32_t a;
    asm("{ .reg .u64 t; cvta.to.shared.u64 t, %1; cvt.u32.u64 %0, t; }" : "=r"(a) : "l"(p));
    return a;
}

#define CP16(saddr, gptr)                                                     \
    asm volatile("cp.async.cg.shared.global [%0], [%1], 16;"                  \
                 :: "r"(saddr), "l"(gptr))

#define MMA(c, a0, a1, a2, a3, b0, b1)                                        \
    asm volatile("mma.sync.aligned.m16n8k16.row.col.f32.f16.f16.f32 "         \
                 "{%0,%1,%2,%3}, {%4,%5,%6,%7}, {%8,%9}, {%0,%1,%2,%3};"      \
                 : "+f"((c)[0]), "+f"((c)[1]), "+f"((c)[2]), "+f"((c)[3])     \
                 : "r"(a0), "r"(a1), "r"(a2), "r"(a3), "r"(b0), "r"(b1))

#define HMUL2(d, x, y)                                                        \
    asm("mul.f16x2 %0, %1, %2;" : "=r"(d) : "r"(x), "r"(y))

#define LDS128U(v, addr)                                                      \
    asm("ld.shared.v4.b32 {%0,%1,%2,%3}, [%4];"                               \
        : "=r"((v).x), "=r"((v).y), "=r"((v).z), "=r"((v).w) : "r"(addr))

// ---------------- merged prep kernel ----------------
// blocks [0,128): z0 frags; [128,256): z1 frags; [256,272): W frags.

__global__ void prep_all(const float* __restrict__ z0, const float* __restrict__ z1,
                         const float* __restrict__ W) {
    const int b = (int)blockIdx.x;
    const int t = (int)threadIdx.x;
    if (b < 128) {
        int gid = b * 256 + t;
        int t_n = gid >> 9, ks = (gid >> 5) & 15, lane = gid & 31;
        int n = t_n * 16 + (lane >> 2);
        int k0 = ks * 16 + (lane & 3) * 2;
        const float* r0 = z0 + (size_t)n * 256;
        const float* r8 = r0 + 8 * 256;
        float2 p0 = *(const float2*)(r0 + k0);
        float2 p1 = *(const float2*)(r8 + k0);
        float2 p2 = *(const float2*)(r0 + k0 + 8);
        float2 p3 = *(const float2*)(r8 + k0 + 8);
        union { __half2 h[4]; uint4 u; } pk;
        pk.h[0] = __floats2half2_rn(p0.x, p0.y);
        pk.h[1] = __floats2half2_rn(p1.x, p1.y);
        pk.h[2] = __floats2half2_rn(p2.x, p2.y);
        pk.h[3] = __floats2half2_rn(p3.x, p3.y);
        g_z0f[gid] = pk.u;
    } else if (b < 256) {
        int gid = (b - 128) * 256 + t;
        int t8 = gid >> 8, ksp = (gid >> 5) & 7, lane = gid & 31;
        int m = t8 * 8 + (lane >> 2);
        int ka = ksp * 32 + (lane & 3) * 2;
        const float* r = z1 + (size_t)m * 256;
        float2 a0 = *(const float2*)(r + ka);
        float2 a1 = *(const float2*)(r + ka + 8);
        float2 b0 = *(const float2*)(r + ka + 16);
        float2 b1 = *(const float2*)(r + ka + 24);
        union { __half2 h[4]; uint4 u; } pk;
        pk.h[0] = __floats2half2_rn(a0.x, a0.y);
        pk.h[1] = __floats2half2_rn(a1.x, a1.y);
        pk.h[2] = __floats2half2_rn(b0.x, b0.y);
        pk.h[3] = __floats2half2_rn(b1.x, b1.y);
        g_z1f[gid] = pk.u;
    } else {
        int gid = (b - 256) * 256 + t;     // 4096 total
        int h = gid >> 5, ksp = (gid >> 2) & 7, c = gid & 3;
        int k0 = ksp * 32 + c * 2;
        const float* r = W + (size_t)h * 256;
        float2 pa0 = *(const float2*)(r + k0);
        float2 pa8 = *(const float2*)(r + k0 + 8);
        float2 pb0 = *(const float2*)(r + k0 + 16);
        float2 pb8 = *(const float2*)(r + k0 + 24);
        union { __half2 h2[4]; uint4 u; } pk;
        pk.h2[0] = __floats2half2_rn(pa0.x, pa0.y);
        pk.h2[1] = __floats2half2_rn(pa8.x, pa8.y);
        pk.h2[2] = __floats2half2_rn(pb0.x, pb0.y);
        pk.h2[3] = __floats2half2_rn(pb8.x, pb8.y);
        g_wf[gid] = pk.u;
    }
}

// ---------------- main kernel ----------------

__global__ void __launch_bounds__(NT, 3)
fc_main(const float* __restrict__ bias, float* __restrict__ out)
{
    extern __shared__ char smem[];
    const uint32_t sbase = smem_u32(smem);
    const int tid = threadIdx.x;
    const int wid = tid >> 5;      // 0..3 = 16m slab
    const int lid = tid & 31;

    const int bid = (int)blockIdx.x;
    const int nt = bid & 63;            // n-tile (16 n)
    const int ms = (bid >> 6) & 15;     // m-supertile (64 m)
    const int h0 = (bid >> 10) << 6;    // h-slice base (64 h)

    // Stage W-frag slice (32KB for h0..h0+63) + bias slice (256B)
    {
        const uint4* gw = g_wf + (size_t)h0 * 32;
        #pragma unroll
        for (int i = 0; i < 16; ++i)
            CP16(sbase + (uint32_t)((tid + i * 128) * 16), gw + tid + i * 128);
        if (tid < 16)
            CP16(sbase + SM_BIAS + (uint32_t)(tid * 16),
                 reinterpret_cast<const uint4*>(bias + h0) + tid);
        asm volatile("cp.async.commit_group;" ::: "memory");
    }

    // Persistent fragments: z0 (64 regs), z1 (64 regs)
    uint4 z0f[16];
    {
        const uint4* p = g_z0f + ((size_t)nt * 16) * 32 + lid;
        #pragma unroll
        for (int ks = 0; ks < 16; ++ks) z0f[ks] = p[ks * 32];
    }
    uint4 z1p[2][8];
    {
        #pragma unroll
        for (int u = 0; u < 2; ++u) {
            const uint4* p = g_z1f + ((size_t)(ms * 8 + wid * 2 + u) * 8) * 32 + lid;
            #pragma unroll
            for (int kp = 0; kp < 8; ++kp) z1p[u][kp] = p[kp * 32];
        }
    }

    asm volatile("cp.async.wait_group 0;" ::: "memory");
    __syncthreads();

    const uint32_t wlane = sbase + (uint32_t)((lid & 3) * 16);
    const int n_lo = nt * 16 + (lid >> 2);
    const int mb   = ms * 64 + wid * 16 + (lid & 3) * 2;
    const size_t obase = (size_t)n_lo * 1024 + mb;

    // Stagger the 64 h's across warps and co-resident CTAs.
    const int hb = ((wid << 4) | (bid & 15)) & 63;

    // Deferred-store state (previous h's packed results)
    float2 pr0, pr1, pr2, pr3;
    float* pop = nullptr;

    #pragma unroll 2
    for (int i = 0; i < 64; ++i) {
        const int hh = (i + hb) & 63;                 // slice-local h
        const uint32_t wbase = wlane + (uint32_t)(hh * 512);

        // acc init = bias (carried through the MMA C operand)
        float bv;
        asm("ld.shared.f32 %0, [%1];" : "=f"(bv) : "r"(sbase + SM_BIAS + (uint32_t)(hh * 4)));
        float acc[2][4];
        #pragma unroll
        for (int u = 0; u < 2; ++u)
            #pragma unroll
            for (int q = 0; q < 4; ++q) acc[u][q] = bv;

        uint4 wc;
        LDS128U(wc, wbase);                           // ksp = 0

        #pragma unroll
        for (int ksp = 0; ksp < 8; ++ksp) {
            uint4 wn = wc;
            if (ksp < 7)
                LDS128U(wn, wbase + (uint32_t)((ksp + 1) * 64));

            // sub-step A: ks = 2*ksp
            {
                uint32_t a0, a1, a2, a3;
                HMUL2(a0, z0f[2 * ksp].x, wc.x);
                HMUL2(a1, z0f[2 * ksp].y, wc.x);
                HMUL2(a2, z0f[2 * ksp].z, wc.y);
                HMUL2(a3, z0f[2 * ksp].w, wc.y);
                MMA(acc[0], a0, a1, a2, a3, z1p[0][ksp].x, z1p[0][ksp].y);
                MMA(acc[1], a0, a1, a2, a3, z1p[1][ksp].x, z1p[1][ksp].y);
            }

            // Deferred stores of PREVIOUS h, issued while MMAs are in flight.
            if (ksp == 1 && pop != nullptr) {
                __stcs(reinterpret_cast<float2*>(pop), pr0);
                __stcs(reinterpret_cast<float2*>(pop + 8), pr1);
                __stcs(reinterpret_cast<float2*>(pop + 8192), pr2);
                __stcs(reinterpret_cast<float2*>(pop + 8200), pr3);
            }

            // sub-step B: ks = 2*ksp+1
            {
                uint32_t a0, a1, a2, a3;
                HMUL2(a0, z0f[2 * ksp + 1].x, wc.z);
                HMUL2(a1, z0f[2 * ksp + 1].y, wc.z);
                HMUL2(a2, z0f[2 * ksp + 1].z, wc.w);
                HMUL2(a3, z0f[2 * ksp + 1].w, wc.w);
                MMA(acc[0], a0, a1, a2, a3, z1p[0][ksp].z, z1p[0][ksp].w);
                MMA(acc[1], a0, a1, a2, a3, z1p[1][ksp].z, z1p[1][ksp].w);
            }
            wc = wn;
        }

        // Pack result (LeakyReLU = max(x, 0.2x)); stores deferred to next h.
        pr0.x = fmaxf(acc[0][0], 0.2f * acc[0][0]);
        pr0.y = fmaxf(acc[0][1], 0.2f * acc[0][1]);
        pr1.x = fmaxf(acc[1][0], 0.2f * acc[1][0]);
        pr1.y = fmaxf(acc[1][1], 0.2f * acc[1][1]);
        pr2.x = fmaxf(acc[0][2], 0.2f * acc[0][2]);
        pr2.y = fmaxf(acc[0][3], 0.2f * acc[0][3]);
        pr3.x = fmaxf(acc[1][2], 0.2f * acc[1][2]);
        pr3.y = fmaxf(acc[1][3], 0.2f * acc[1][3]);
        pop = out + (((size_t)(h0 + hh)) << 20) + obase;
    }

    // Drain last h's stores.
    __stcs(reinterpret_cast<float2*>(pop), pr0);
    __stcs(reinterpret_cast<float2*>(pop + 8), pr1);
    __stcs(reinterpret_cast<float2*>(pop + 8192), pr2);
    __stcs(reinterpret_cast<float2*>(pop + 8200), pr3);
}

extern "C" void kernel_launch(void* const* d_in, const int* in_sizes, int n_in,
                              void* d_out, int out_size) {
    const float* z0   = (const float*)d_in[0];   // (1, 1024, 256)
    const float* z1   = (const float*)d_in[1];   // (1, 1024, 256)
    const float* W    = (const float*)d_in[2];   // (128, 256)
    const float* bias = (const float*)d_in[3];   // (128,)
    float* out = (float*)d_out;                  // (1, 128, 1024, 1024)

    prep_all<<<272, 256>>>(z0, z1, W);

    cudaFuncSetAttribute(fc_main, cudaFuncAttributeMaxDynamicSharedMemorySize, SMEM_BYTES);
    // grid: 64 nt x 16 ms x 2 hs = 2048 CTAs
    fc_main<<<2048, NT, SMEM_BYTES>>>(bias, out);
}

// round 17
// speedup vs baseline: 1.0978x; 1.0978x over previous
#include <cuda_runtime.h>
#include <cuda_fp16.h>
#include <cstdint>
#include <cstddef>

// out[h,n,m] = LeakyReLU_{0.2}( sum_d z0[n,d]*z1[m,d]*W[h,d] + bias[h] )
// N=M=1024, D=256, H=128, fp32 in/out.
//
// v17 = v15 engine with u=4 (warp tile 16n x 32m): halves chip-wide HMUL2
// (fma pipe 63->32us) and W-LDS traffic (63->32us), the two co-bound pipes.
// 2 CTAs/SM (z1p = 128 regs). Direct stores (deferred dropped to save regs).
// CTA = 16n x 128m x 64h; grid = 64nt x 8ms x 2hs = 1024.

#define NT 128

__device__ uint4 g_z0f[64 * 16 * 32];      // [n16tile][ks][lane] {a0,a1,a2,a3}  512KB
__device__ uint4 g_z1f[128 * 8 * 32];      // [m8tile][kspair][lane]             512KB
__device__ uint4 g_wf[128 * 8 * 4];        // [h][ksp][c] {w01a,w89a,w01b,w89b}  64KB

static constexpr int SM_BIAS = 32768;            // after 32KB W slice
static constexpr int SMEM_BYTES = 32768 + 256;

__device__ __forceinline__ uint32_t smem_u32(const void* p) {
    uint32_t a;
    asm("{ .reg .u64 t; cvta.to.shared.u64 t, %1; cvt.u32.u64 %0, t; }" : "=r"(a) : "l"(p));
    return a;
}

#define CP16(saddr, gptr)                                                     \
    asm volatile("cp.async.cg.shared.global [%0], [%1], 16;"                  \
                 :: "r"(saddr), "l"(gptr))

#define MMA(c, a0, a1, a2, a3, b0, b1)                                        \
    asm volatile("mma.sync.aligned.m16n8k16.row.col.f32.f16.f16.f32 "         \
                 "{%0,%1,%2,%3}, {%4,%5,%6,%7}, {%8,%9}, {%0,%1,%2,%3};"      \
                 : "+f"((c)[0]), "+f"((c)[1]), "+f"((c)[2]), "+f"((c)[3])     \
                 : "r"(a0), "r"(a1), "r"(a2), "r"(a3), "r"(b0), "r"(b1))

#define HMUL2(d, x, y)                                                        \
    asm("mul.f16x2 %0, %1, %2;" : "=r"(d) : "r"(x), "r"(y))

#define LDS128U(v, addr)                                                      \
    asm("ld.shared.v4.b32 {%0,%1,%2,%3}, [%4];"                               \
        : "=r"((v).x), "=r"((v).y), "=r"((v).z), "=r"((v).w) : "r"(addr))

// ---------------- merged prep kernel ----------------
// blocks [0,128): z0 frags; [128,256): z1 frags; [256,272): W frags.

__global__ void prep_all(const float* __restrict__ z0, const float* __restrict__ z1,
                         const float* __restrict__ W) {
    const int b = (int)blockIdx.x;
    const int t = (int)threadIdx.x;
    if (b < 128) {
        int gid = b * 256 + t;
        int t_n = gid >> 9, ks = (gid >> 5) & 15, lane = gid & 31;
        int n = t_n * 16 + (lane >> 2);
        int k0 = ks * 16 + (lane & 3) * 2;
        const float* r0 = z0 + (size_t)n * 256;
        const float* r8 = r0 + 8 * 256;
        float2 p0 = *(const float2*)(r0 + k0);
        float2 p1 = *(const float2*)(r8 + k0);
        float2 p2 = *(const float2*)(r0 + k0 + 8);
        float2 p3 = *(const float2*)(r8 + k0 + 8);
        union { __half2 h[4]; uint4 u; } pk;
        pk.h[0] = __floats2half2_rn(p0.x, p0.y);
        pk.h[1] = __floats2half2_rn(p1.x, p1.y);
        pk.h[2] = __floats2half2_rn(p2.x, p2.y);
        pk.h[3] = __floats2half2_rn(p3.x, p3.y);
        g_z0f[gid] = pk.u;
    } else if (b < 256) {
        int gid = (b - 128) * 256 + t;
        int t8 = gid >> 8, ksp = (gid >> 5) & 7, lane = gid & 31;
        int m = t8 * 8 + (lane >> 2);
        int ka = ksp * 32 + (lane & 3) * 2;
        const float* r = z1 + (size_t)m * 256;
        float2 a0 = *(const float2*)(r + ka);
        float2 a1 = *(const float2*)(r + ka + 8);
        float2 b0 = *(const float2*)(r + ka + 16);
        float2 b1 = *(const float2*)(r + ka + 24);
        union { __half2 h[4]; uint4 u; } pk;
        pk.h[0] = __floats2half2_rn(a0.x, a0.y);
        pk.h[1] = __floats2half2_rn(a1.x, a1.y);
        pk.h[2] = __floats2half2_rn(b0.x, b0.y);
        pk.h[3] = __floats2half2_rn(b1.x, b1.y);
        g_z1f[gid] = pk.u;
    } else {
        int gid = (b - 256) * 256 + t;     // 4096 total
        int h = gid >> 5, ksp = (gid >> 2) & 7, c = gid & 3;
        int k0 = ksp * 32 + c * 2;
        const float* r = W + (size_t)h * 256;
        float2 pa0 = *(const float2*)(r + k0);
        float2 pa8 = *(const float2*)(r + k0 + 8);
        float2 pb0 = *(const float2*)(r + k0 + 16);
        float2 pb8 = *(const float2*)(r + k0 + 24);
        union { __half2 h2[4]; uint4 u; } pk;
        pk.h2[0] = __floats2half2_rn(pa0.x, pa0.y);
        pk.h2[1] = __floats2half2_rn(pa8.x, pa8.y);
        pk.h2[2] = __floats2half2_rn(pb0.x, pb0.y);
        pk.h2[3] = __floats2half2_rn(pb8.x, pb8.y);
        g_wf[gid] = pk.u;
    }
}

// ---------------- main kernel ----------------

__global__ void __launch_bounds__(NT, 2)
fc_main(const float* __restrict__ bias, float* __restrict__ out)
{
    extern __shared__ char smem[];
    const uint32_t sbase = smem_u32(smem);
    const int tid = threadIdx.x;
    const int wid = tid >> 5;      // 0..3 = 32m slab
    const int lid = tid & 31;

    const int bid = (int)blockIdx.x;
    const int nt = bid & 63;            // n-tile (16 n)
    const int ms = (bid >> 6) & 7;      // m-supertile (128 m)
    const int h0 = (bid >> 9) << 6;     // h-slice base (64 h)

    // Stage W-frag slice (32KB for h0..h0+63) + bias slice (256B)
    {
        const uint4* gw = g_wf + (size_t)h0 * 32;
        #pragma unroll
        for (int i = 0; i < 16; ++i)
            CP16(sbase + (uint32_t)((tid + i * 128) * 16), gw + tid + i * 128);
        if (tid < 16)
            CP16(sbase + SM_BIAS + (uint32_t)(tid * 16),
                 reinterpret_cast<const uint4*>(bias + h0) + tid);
        asm volatile("cp.async.commit_group;" ::: "memory");
    }

    // Persistent fragments: z0 (64 regs), z1 (128 regs)
    uint4 z0f[16];
    {
        const uint4* p = g_z0f + ((size_t)nt * 16) * 32 + lid;
        #pragma unroll
        for (int ks = 0; ks < 16; ++ks) z0f[ks] = p[ks * 32];
    }
    uint4 z1p[4][8];
    {
        #pragma unroll
        for (int u = 0; u < 4; ++u) {
            const uint4* p = g_z1f + ((size_t)(ms * 16 + wid * 4 + u) * 8) * 32 + lid;
            #pragma unroll
            for (int kp = 0; kp < 8; ++kp) z1p[u][kp] = p[kp * 32];
        }
    }

    asm volatile("cp.async.wait_group 0;" ::: "memory");
    __syncthreads();

    const uint32_t wlane = sbase + (uint32_t)((lid & 3) * 16);
    const int n_lo = nt * 16 + (lid >> 2);
    const int mb   = ms * 128 + wid * 32 + (lid & 3) * 2;
    float* const ob0 = out + (size_t)n_lo * 1024 + mb;

    // Stagger the 64 h's across warps and co-resident CTAs.
    const int hb = ((wid << 4) | (bid & 15)) & 63;

    #pragma unroll 1
    for (int i = 0; i < 64; ++i) {
        const int hh = (i + hb) & 63;                 // slice-local h
        const uint32_t wbase = wlane + (uint32_t)(hh * 512);

        // acc init = bias (carried through the MMA C operand)
        float bv;
        asm("ld.shared.f32 %0, [%1];" : "=f"(bv) : "r"(sbase + SM_BIAS + (uint32_t)(hh * 4)));
        float acc[4][4];
        #pragma unroll
        for (int u = 0; u < 4; ++u)
            #pragma unroll
            for (int q = 0; q < 4; ++q) acc[u][q] = bv;

        uint4 wc;
        LDS128U(wc, wbase);                           // ksp = 0

        #pragma unroll
        for (int ksp = 0; ksp < 8; ++ksp) {
            uint4 wn = wc;
            if (ksp < 7)
                LDS128U(wn, wbase + (uint32_t)((ksp + 1) * 64));

            // sub-step A: ks = 2*ksp
            {
                uint32_t a0, a1, a2, a3;
                HMUL2(a0, z0f[2 * ksp].x, wc.x);
                HMUL2(a1, z0f[2 * ksp].y, wc.x);
                HMUL2(a2, z0f[2 * ksp].z, wc.y);
                HMUL2(a3, z0f[2 * ksp].w, wc.y);
                MMA(acc[0], a0, a1, a2, a3, z1p[0][ksp].x, z1p[0][ksp].y);
                MMA(acc[1], a0, a1, a2, a3, z1p[1][ksp].x, z1p[1][ksp].y);
                MMA(acc[2], a0, a1, a2, a3, z1p[2][ksp].x, z1p[2][ksp].y);
                MMA(acc[3], a0, a1, a2, a3, z1p[3][ksp].x, z1p[3][ksp].y);
            }
            // sub-step B: ks = 2*ksp+1
            {
                uint32_t a0, a1, a2, a3;
                HMUL2(a0, z0f[2 * ksp + 1].x, wc.z);
                HMUL2(a1, z0f[2 * ksp + 1].y, wc.z);
                HMUL2(a2, z0f[2 * ksp + 1].z, wc.w);
                HMUL2(a3, z0f[2 * ksp + 1].w, wc.w);
                MMA(acc[0], a0, a1, a2, a3, z1p[0][ksp].z, z1p[0][ksp].w);
                MMA(acc[1], a0, a1, a2, a3, z1p[1][ksp].z, z1p[1][ksp].w);
                MMA(acc[2], a0, a1, a2, a3, z1p[2][ksp].z, z1p[2][ksp].w);
                MMA(acc[3], a0, a1, a2, a3, z1p[3][ksp].z, z1p[3][ksp].w);
            }
            wc = wn;
        }

        // Epilogue: LeakyReLU = max(x, 0.2x); streaming STG.64 stores.
        float* op = ob0 + (((size_t)(h0 + hh)) << 20);
        #pragma unroll
        for (int u = 0; u < 4; ++u) {
            float2 lo, hi;
            lo.x = fmaxf(acc[u][0], 0.2f * acc[u][0]);
            lo.y = fmaxf(acc[u][1], 0.2f * acc[u][1]);
            hi.x = fmaxf(acc[u][2], 0.2f * acc[u][2]);
            hi.y = fmaxf(acc[u][3], 0.2f * acc[u][3]);
            __stcs(reinterpret_cast<float2*>(op + u * 8), lo);
            __stcs(reinterpret_cast<float2*>(op + 8192 + u * 8), hi);
        }
    }
}

extern "C" void kernel_launch(void* const* d_in, const int* in_sizes, int n_in,
                              void* d_out, int out_size) {
    const float* z0   = (const float*)d_in[0];   // (1, 1024, 256)
    const float* z1   = (const float*)d_in[1];   // (1, 1024, 256)
    const float* W    = (const float*)d_in[2];   // (128, 256)
    const float* bias = (const float*)d_in[3];   // (128,)
    float* out = (float*)d_out;                  // (1, 128, 1024, 1024)

    prep_all<<<272, 256>>>(z0, z1, W);

    cudaFuncSetAttribute(fc_main, cudaFuncAttributeMaxDynamicSharedMemorySize, SMEM_BYTES);
    // grid: 64 nt x 8 ms x 2 hs = 1024 CTAs
    fc_main<<<1024, NT, SMEM_BYTES>>>(bias, out);
}